// round 16
// baseline (speedup 1.0000x reference)
#include <cuda_runtime.h>
#include <cuda_bf16.h>
#include <math.h>

// Shapes (fixed dataset):
//   x_all: [100000, 256] f32, n_id: [50000] i32, edge_index: [2, 300000] i32
//   W_sage: [256,256] f32, b_sage: [256] f32, W_cls: [3,256] f32, b_cls: [3] f32
//   out: [50000, 3] f32 (log_softmax)
//
// out = log_softmax( mean_j( x[j] @ Wc ) + bc ); shift-invariance -> 2 diffs.
// R16: replace fp32 REDG aggregation with scatter-index / gather-value:
//   k_init    : zero deg + fuse diff weights             (PDL)
//   k_scatter : bucket[dst][atomicAdd(deg[dst])] = src   (int atomics only)
//   k_z       : z[i] = x_all[n_id[i]] @ Wd               (heavy loads pre-wait,
//               overlap the scatter drain)
//   k_gf      : per node: sum z over bucket + self, softmax  (NO fp atomics)
#define NMAX 50000
#define FDIM 256
#define F4   64
#define CCLS 2
#define CAP  96      // Poisson(6): P(deg>=96) ~ 1e-60

__device__ float  g_Wd    [CCLS * FDIM];
__device__ float  g_bd    [CCLS];
__device__ float2 g_z2    [NMAX];
__device__ int    g_deg   [NMAX];          // zeroed by k_init each replay
__device__ int    g_bucket[NMAX * CAP];    // never cleared; stale entries are
                                           // valid old indices (<N), masked off

__device__ __forceinline__ void pdl_wait()    { asm volatile("griddepcontrol.wait;" ::: "memory"); }
__device__ __forceinline__ void pdl_trigger() { asm volatile("griddepcontrol.launch_dependents;" ::: "memory"); }

// ---------------------------------------------------------------------------
// Kernel 0: zero deg + parallel fusion of diff weights.
//   Wd[c][k] = sum_h W_sage[k,h]*(W_cls[c,h]-W_cls[2,h]), c in {0,1}
// Input loads pre-wait; deg zeroing + Wd/bd stores post-wait (k_gf(i-1) reads
// deg/bd before its trigger, so post-wait writes are race-free).
// ---------------------------------------------------------------------------
__global__ void k_init(const float* __restrict__ W_sage,
                       const float* __restrict__ b_sage,
                       const float* __restrict__ W_cls,
                       const float* __restrict__ b_cls, int N) {
    int gid  = blockIdx.x * blockDim.x + threadIdx.x;
    int ww   = gid >> 5;
    int lane = gid & 31;
    const unsigned full = 0xffffffffu;

    // pre-wait prologue: external-input loads only
    float4 a0, a1, e0, e1;
    bool wtask = (ww < CCLS * FDIM);
    bool btask = (!wtask) && (ww < CCLS * FDIM + CCLS);
    if (wtask) {
        int c = ww >> 8, k = ww & 255;
        const float4* wrow = reinterpret_cast<const float4*>(W_sage + k * FDIM);
        const float4* crow = reinterpret_cast<const float4*>(W_cls  + c * FDIM);
        const float4* rrow = reinterpret_cast<const float4*>(W_cls  + 2 * FDIM);
        a0 = __ldg(&wrow[lane]);      a1 = __ldg(&wrow[lane + 32]);
        float4 b0 = __ldg(&crow[lane]), b1 = __ldg(&crow[lane + 32]);
        float4 r0 = __ldg(&rrow[lane]), r1 = __ldg(&rrow[lane + 32]);
        e0 = make_float4(b0.x-r0.x, b0.y-r0.y, b0.z-r0.z, b0.w-r0.w);
        e1 = make_float4(b1.x-r1.x, b1.y-r1.y, b1.z-r1.z, b1.w-r1.w);
    } else if (btask) {
        int c = ww - CCLS * FDIM;
        const float4* brow = reinterpret_cast<const float4*>(b_sage);
        const float4* crow = reinterpret_cast<const float4*>(W_cls + c * FDIM);
        const float4* rrow = reinterpret_cast<const float4*>(W_cls + 2 * FDIM);
        a0 = __ldg(&brow[lane]);      a1 = __ldg(&brow[lane + 32]);
        float4 b0 = __ldg(&crow[lane]), b1 = __ldg(&crow[lane + 32]);
        float4 r0 = __ldg(&rrow[lane]), r1 = __ldg(&rrow[lane + 32]);
        e0 = make_float4(b0.x-r0.x, b0.y-r0.y, b0.z-r0.z, b0.w-r0.w);
        e1 = make_float4(b1.x-r1.x, b1.y-r1.y, b1.z-r1.z, b1.w-r1.w);
    }

    pdl_wait();   // k_gf(i-1) has read deg/bd (its trigger precedes our release)

    if (gid < N) g_deg[gid] = 0;

    if (wtask || btask) {
        float s = fmaf(a0.x, e0.x, fmaf(a0.y, e0.y, fmaf(a0.z, e0.z, a0.w * e0.w)))
                + fmaf(a1.x, e1.x, fmaf(a1.y, e1.y, fmaf(a1.z, e1.z, a1.w * e1.w)));
        #pragma unroll
        for (int off = 16; off > 0; off >>= 1)
            s += __shfl_down_sync(full, s, off);
        if (lane == 0) {
            if (wtask) {
                g_Wd[(ww >> 8) * FDIM + (ww & 255)] = s;
            } else {
                int c = ww - CCLS * FDIM;
                g_bd[c] = s + __ldg(&b_cls[c]) - __ldg(&b_cls[2]);
            }
        }
    }
    pdl_trigger();
}

// ---------------------------------------------------------------------------
// Kernel 1: bucket scatter. One edge per thread, INT atomics only.
// ---------------------------------------------------------------------------
__global__ void k_scatter(const int* __restrict__ src,
                          const int* __restrict__ dst, int E) {
    int e = blockIdx.x * blockDim.x + threadIdx.x;
    int s = 0, d = 0;
    bool ok = (e < E);
    if (ok) { s = __ldg(&src[e]); d = __ldg(&dst[e]); }   // pre-wait
    pdl_wait();   // g_deg zeroed
    if (ok) {
        int pos = atomicAdd(&g_deg[d], 1);
        if (pos < CAP) g_bucket[d * CAP + pos] = s;
    }
    pdl_trigger();
}

// ---------------------------------------------------------------------------
// Kernel 2: project, FOUR nodes per warp (8 independent LDG.128/lane pre-wait;
// the heavy 51MB prologue also hides k_scatter's atomic drain).
//   z[i] = x_all[n_id[i]] @ Wd (2 floats)
// ---------------------------------------------------------------------------
__global__ void k_z(const float4* __restrict__ x_all4,
                    const int* __restrict__ n_id, int N) {
    __shared__ float sW[CCLS][FDIM];
    int t    = threadIdx.x;
    int wp   = (blockIdx.x * blockDim.x + t) >> 5;
    int lane = t & 31;
    int w0 = wp * 4;

    float4 d0a, d0b, d1a, d1b, d2a, d2b, d3a, d3b;
    const float4 Z = make_float4(0.f, 0.f, 0.f, 0.f);
    d0a = d0b = d1a = d1b = d2a = d2b = d3a = d3b = Z;
    bool h0 = (w0     < N);
    bool h1 = (w0 + 1 < N);
    bool h2 = (w0 + 2 < N);
    bool h3 = (w0 + 3 < N);
    if (h0) {
        const float4* xp = x_all4 + (long long)__ldg(&n_id[w0]) * F4;
        d0a = __ldg(&xp[lane]); d0b = __ldg(&xp[lane + 32]);
    }
    if (h1) {
        const float4* xp = x_all4 + (long long)__ldg(&n_id[w0 + 1]) * F4;
        d1a = __ldg(&xp[lane]); d1b = __ldg(&xp[lane + 32]);
    }
    if (h2) {
        const float4* xp = x_all4 + (long long)__ldg(&n_id[w0 + 2]) * F4;
        d2a = __ldg(&xp[lane]); d2b = __ldg(&xp[lane + 32]);
    }
    if (h3) {
        const float4* xp = x_all4 + (long long)__ldg(&n_id[w0 + 3]) * F4;
        d3a = __ldg(&xp[lane]); d3b = __ldg(&xp[lane + 32]);
    }

    pdl_wait();   // g_Wd ready
    for (int idx = t; idx < CCLS * FDIM; idx += blockDim.x)
        sW[idx >> 8][idx & 255] = g_Wd[idx];
    __syncthreads();

    if (!h0) { pdl_trigger(); return; }

    int k0 = lane * 4, k1 = (lane + 32) * 4;
    float w00 = sW[0][k0], w01 = sW[0][k0+1], w02 = sW[0][k0+2], w03 = sW[0][k0+3];
    float w10 = sW[1][k0], w11 = sW[1][k0+1], w12 = sW[1][k0+2], w13 = sW[1][k0+3];
    float v00 = sW[0][k1], v01 = sW[0][k1+1], v02 = sW[0][k1+2], v03 = sW[0][k1+3];
    float v10 = sW[1][k1], v11 = sW[1][k1+1], v12 = sW[1][k1+2], v13 = sW[1][k1+3];

    #define DOT2(ra, rb, o0, o1)                                                \
        o0 = fmaf((ra).x,w00, fmaf((ra).y,w01, fmaf((ra).z,w02, (ra).w*w03)));  \
        o1 = fmaf((ra).x,w10, fmaf((ra).y,w11, fmaf((ra).z,w12, (ra).w*w13)));  \
        o0 = fmaf((rb).x,v00, fmaf((rb).y,v01, fmaf((rb).z,v02, fmaf((rb).w,v03, o0)))); \
        o1 = fmaf((rb).x,v10, fmaf((rb).y,v11, fmaf((rb).z,v12, fmaf((rb).w,v13, o1))));

    float x0, x1, y0, y1, u0, u1, q0, q1;
    DOT2(d0a, d0b, x0, x1)
    DOT2(d1a, d1b, y0, y1)
    DOT2(d2a, d2b, u0, u1)
    DOT2(d3a, d3b, q0, q1)
    #undef DOT2

    const unsigned full = 0xffffffffu;
    #pragma unroll
    for (int off = 16; off > 0; off >>= 1) {
        x0 += __shfl_down_sync(full, x0, off);
        x1 += __shfl_down_sync(full, x1, off);
        y0 += __shfl_down_sync(full, y0, off);
        y1 += __shfl_down_sync(full, y1, off);
        u0 += __shfl_down_sync(full, u0, off);
        u1 += __shfl_down_sync(full, u1, off);
        q0 += __shfl_down_sync(full, q0, off);
        q1 += __shfl_down_sync(full, q1, off);
    }
    if (lane == 0) {
        g_z2[w0] = make_float2(x0, x1);
        if (h1) g_z2[w0+1] = make_float2(y0, y1);
        if (h2) g_z2[w0+2] = make_float2(u0, u1);
        if (h3) g_z2[w0+3] = make_float2(q0, q1);
    }
    pdl_trigger();
}

// ---------------------------------------------------------------------------
// Kernel 3: gather + finalize. One thread per node, NO fp atomics.
//   sum = z[i] + sum_{j<deg} z[bucket[i][j]];  cnt = deg+1
// First 8 bucket entries prefetched unconditionally (stale entries are valid
// old indices < N; their contributions are masked off), shortening the load
// chain to deg -> (bucket||z-self) -> z.
// ---------------------------------------------------------------------------
__global__ void k_gf(float* __restrict__ out, int N) {
    int i = blockIdx.x * blockDim.x + threadIdx.x;
    pdl_wait();   // deg/bucket/z all visible
    if (i >= N) return;

    int deg = g_deg[i];
    const int4* bp = reinterpret_cast<const int4*>(g_bucket + (long long)i * CAP);
    int4 b0 = __ldg(&bp[0]);          // speculative (mask later)
    int4 b1 = __ldg(&bp[1]);
    float2 self = __ldg(&g_z2[i]);
    int degc = deg < CAP ? deg : CAP;

    float2 z0 = __ldg(&g_z2[b0.x]);
    float2 z1 = __ldg(&g_z2[b0.y]);
    float2 z2 = __ldg(&g_z2[b0.z]);
    float2 z3 = __ldg(&g_z2[b0.w]);
    float2 z4 = __ldg(&g_z2[b1.x]);
    float2 z5 = __ldg(&g_z2[b1.y]);
    float2 z6 = __ldg(&g_z2[b1.z]);
    float2 z7 = __ldg(&g_z2[b1.w]);

    float a0 = self.x, a1 = self.y;
    float c0 = 0.f,    c1 = 0.f;
    a0 += (0 < degc) ? z0.x : 0.f;  a1 += (0 < degc) ? z0.y : 0.f;
    c0 += (1 < degc) ? z1.x : 0.f;  c1 += (1 < degc) ? z1.y : 0.f;
    a0 += (2 < degc) ? z2.x : 0.f;  a1 += (2 < degc) ? z2.y : 0.f;
    c0 += (3 < degc) ? z3.x : 0.f;  c1 += (3 < degc) ? z3.y : 0.f;
    a0 += (4 < degc) ? z4.x : 0.f;  a1 += (4 < degc) ? z4.y : 0.f;
    c0 += (5 < degc) ? z5.x : 0.f;  c1 += (5 < degc) ? z5.y : 0.f;
    a0 += (6 < degc) ? z6.x : 0.f;  a1 += (6 < degc) ? z6.y : 0.f;
    c0 += (7 < degc) ? z7.x : 0.f;  c1 += (7 < degc) ? z7.y : 0.f;

    for (int j = 8; j < degc; j += 4) {
        int4 b = __ldg(&bp[j >> 2]);
        float2 t0 = __ldg(&g_z2[b.x]);
        float2 t1 = __ldg(&g_z2[b.y]);
        float2 t2 = __ldg(&g_z2[b.z]);
        float2 t3 = __ldg(&g_z2[b.w]);
        a0 += t0.x;                           a1 += t0.y;                 // j < degc guaranteed
        c0 += (j + 1 < degc) ? t1.x : 0.f;    c1 += (j + 1 < degc) ? t1.y : 0.f;
        a0 += (j + 2 < degc) ? t2.x : 0.f;    a1 += (j + 2 < degc) ? t2.y : 0.f;
        c0 += (j + 3 < degc) ? t3.x : 0.f;    c1 += (j + 3 < degc) ? t3.y : 0.f;
    }
    float s0 = a0 + c0;
    float s1 = a1 + c1;
    float bd0 = g_bd[0], bd1 = g_bd[1];

    pdl_trigger();   // all global reads done -> next replay's k_init may start

    float inv = __frcp_rn((float)(deg + 1));
    float gg0 = fmaf(s0, inv, bd0);
    float gg1 = fmaf(s1, inv, bd1);
    float m   = fmaxf(0.0f, fmaxf(gg0, gg1));
    float lse = m + __logf(__expf(gg0 - m) + __expf(gg1 - m) + __expf(-m));
    out[i * 3 + 0] = gg0 - lse;
    out[i * 3 + 1] = gg1 - lse;
    out[i * 3 + 2] = -lse;
}

// ---------------------------------------------------------------------------
static inline void launch_pdl(void* fn, dim3 grid, dim3 block,
                              void** args, bool pdl_in) {
    cudaLaunchConfig_t cfg = {};
    cfg.gridDim  = grid;
    cfg.blockDim = block;
    cfg.dynamicSmemBytes = 0;
    cfg.stream = 0;
    cudaLaunchAttribute attr[1];
    int nattr = 0;
    if (pdl_in) {
        attr[0].id = cudaLaunchAttributeProgrammaticStreamSerialization;
        attr[0].val.programmaticStreamSerializationAllowed = 1;
        nattr = 1;
    }
    cfg.attrs = attr;
    cfg.numAttrs = nattr;
    cudaLaunchKernelExC(&cfg, fn, args);
}

extern "C" void kernel_launch(void* const* d_in, const int* in_sizes, int n_in,
                              void* d_out, int out_size) {
    const float* x_all  = (const float*)d_in[0];
    const int*   n_id   = (const int*)  d_in[1];
    const int*   eidx   = (const int*)  d_in[2];
    const float* W_sage = (const float*)d_in[3];
    const float* b_sage = (const float*)d_in[4];
    const float* W_cls  = (const float*)d_in[5];
    const float* b_cls  = (const float*)d_in[6];
    float* out = (float*)d_out;

    int N = in_sizes[1];          // 50000
    int E = in_sizes[2] / 2;      // 300000
    const int* src = eidx;        // edge_index[0, :]
    const int* dst = eidx + E;    // edge_index[1, :]

    // k_init: covers N deg-zeros AND 514 fusion warps
    {
        int threads = N;
        int wth = (CCLS * FDIM + CCLS) * 32;
        if (wth > threads) threads = wth;
        dim3 g((threads + 255) / 256), b(256);
        void* args[] = {(void*)&W_sage, (void*)&b_sage, (void*)&W_cls, (void*)&b_cls, (void*)&N};
        launch_pdl((void*)k_init, g, b, args, true);
    }
    // k_scatter: one edge per thread (int atomics)
    {
        dim3 g((E + 255) / 256), b(256);
        void* args[] = {(void*)&src, (void*)&dst, (void*)&E};
        launch_pdl((void*)k_scatter, g, b, args, true);
    }
    // k_z: FOUR nodes per warp (prologue overlaps scatter drain)
    {
        const float4* x4 = reinterpret_cast<const float4*>(x_all);
        int warps = (N + 3) / 4;
        long long th = (long long)warps * 32;
        dim3 g((unsigned)((th + 255) / 256)), b(256);
        void* args[] = {(void*)&x4, (void*)&n_id, (void*)&N};
        launch_pdl((void*)k_z, g, b, args, true);
    }
    // k_gf: one thread per node, gather + softmax
    {
        dim3 g((N + 255) / 256), b(256);
        void* args[] = {(void*)&out, (void*)&N};
        launch_pdl((void*)k_gf, g, b, args, true);
    }
}